// round 2
// baseline (speedup 1.0000x reference)
#include <cuda_runtime.h>
#include <cuda_bf16.h>
#include <cstdint>

// Problem constants (fixed shapes from reference)
#define SQ     8192
#define DMODEL 1152
#define NH     16
#define DH     72
#define QKV3   3456
#define LCHUNK 1024
#define NCHUNK 8

// Scratch (device globals; no cudaMalloc allowed)
__device__ float g_qkv[(size_t)SQ * QKV3];       // [S, 3, H, DH]
__device__ float g_attn[(size_t)SQ * DMODEL];    // [S, H*DH]

// ---------------------------------------------------------------------------
// Packed f32x2 helpers (Blackwell FFMA2 — only reachable via PTX)
// ---------------------------------------------------------------------------
typedef unsigned long long ull;

__device__ __forceinline__ ull ffma2(ull a, ull b, ull c) {
    ull d;
    asm("fma.rn.f32x2 %0, %1, %2, %3;" : "=l"(d) : "l"(a), "l"(b), "l"(c));
    return d;
}
__device__ __forceinline__ ull fmul2(ull a, ull b) {
    ull d;
    asm("mul.rn.f32x2 %0, %1, %2;" : "=l"(d) : "l"(a), "l"(b));
    return d;
}
__device__ __forceinline__ ull pack2(float lo, float hi) {
    ull r;
    asm("mov.b64 %0, {%1, %2};" : "=l"(r) : "f"(lo), "f"(hi));
    return r;
}
__device__ __forceinline__ float2 unpack2(ull v) {
    float2 f;
    asm("mov.b64 {%0, %1}, %2;" : "=f"(f.x), "=f"(f.y) : "l"(v));
    return f;
}

// ---------------------------------------------------------------------------
// SGEMM (f32x2): C[M,N] = A[M,K] @ W[N,K]^T + bias[N]
// 128x128x8 tile, 256 threads, 8x8 per-thread microtile via 32 FFMA2.
// A stored DUPLICATED in smem so packed (a,a) pairs load directly.
// ---------------------------------------------------------------------------
#define GBM 128
#define GBN 128
#define GBK 8

__global__ __launch_bounds__(256) void sgemm_bias_kernel(
    const float* __restrict__ A, const float* __restrict__ W,
    const float* __restrict__ bias, float* __restrict__ C,
    int M, int N, int K)
{
    __shared__ float As2[GBK][2 * GBM];   // duplicated: [k][2m]=[k][2m+1]=A
    __shared__ float Bs[GBK][GBN];

    const int tid = threadIdx.x;
    const int bm = blockIdx.y * GBM;
    const int bn = blockIdx.x * GBN;

    const int lr = tid >> 1;            // 0..127
    const int lc = (tid & 1) * 4;       // 0 or 4
    const float* Aptr = A + (size_t)(bm + lr) * K + lc;
    const float* Wptr = W + (size_t)(bn + lr) * K + lc;

    const int ty = tid >> 4, tx = tid & 15;
    const int rm = ty * 8, rn = tx * 8;

    ull acc[8][4];
#pragma unroll
    for (int i = 0; i < 8; i++)
#pragma unroll
        for (int j = 0; j < 4; j++) acc[i][j] = 0ULL;

    float4 av = *(const float4*)(Aptr);
    float4 wv = *(const float4*)(Wptr);

    for (int k0 = 0; k0 < K; k0 += GBK) {
        *(float2*)&As2[lc + 0][2 * lr] = make_float2(av.x, av.x);
        *(float2*)&As2[lc + 1][2 * lr] = make_float2(av.y, av.y);
        *(float2*)&As2[lc + 2][2 * lr] = make_float2(av.z, av.z);
        *(float2*)&As2[lc + 3][2 * lr] = make_float2(av.w, av.w);
        Bs[lc + 0][lr] = wv.x; Bs[lc + 1][lr] = wv.y;
        Bs[lc + 2][lr] = wv.z; Bs[lc + 3][lr] = wv.w;
        __syncthreads();

        if (k0 + GBK < K) {
            av = *(const float4*)(Aptr + k0 + GBK);
            wv = *(const float4*)(Wptr + k0 + GBK);
        }

#pragma unroll
        for (int kk = 0; kk < GBK; kk++) {
            // a: 8 duplicated pairs = 4x LDS.128 (ulonglong2 = 2 pairs)
            const ulonglong2* ap = (const ulonglong2*)&As2[kk][2 * rm];
            ulonglong2 a01 = ap[0], a23 = ap[1], a45 = ap[2], a67 = ap[3];
            // b: 8 floats = 4 natural pairs = 2x LDS.128
            const ulonglong2* bp = (const ulonglong2*)&Bs[kk][rn];
            ulonglong2 b01 = bp[0], b23 = bp[1];
            ull a2[8] = {a01.x, a01.y, a23.x, a23.y, a45.x, a45.y, a67.x, a67.y};
            ull b2[4] = {b01.x, b01.y, b23.x, b23.y};
#pragma unroll
            for (int i = 0; i < 8; i++)
#pragma unroll
                for (int j = 0; j < 4; j++)
                    acc[i][j] = ffma2(a2[i], b2[j], acc[i][j]);
        }
        __syncthreads();
    }

#pragma unroll
    for (int i = 0; i < 8; i++) {
        const size_t row = (size_t)(bm + rm + i);
        float* cptr = C + row * N + bn + rn;
        const float* bptr = bias + bn + rn;
#pragma unroll
        for (int j2 = 0; j2 < 2; j2++) {
            float2 f0 = unpack2(acc[i][j2 * 2 + 0]);
            float2 f1 = unpack2(acc[i][j2 * 2 + 1]);
            float4 o;
            o.x = f0.x + bptr[j2 * 4 + 0];
            o.y = f0.y + bptr[j2 * 4 + 1];
            o.z = f1.x + bptr[j2 * 4 + 2];
            o.w = f1.y + bptr[j2 * 4 + 3];
            *(float4*)(cptr + j2 * 4) = o;
        }
    }
}

// ---------------------------------------------------------------------------
// RoPE on q and k in-place inside g_qkv. Layout [S, 3, H, DH].
// ---------------------------------------------------------------------------
__global__ __launch_bounds__(256) void rope_kernel(
    float* __restrict__ qkv, const float* __restrict__ cosp,
    const float* __restrict__ sinp)
{
    const int idx = blockIdx.x * blockDim.x + threadIdx.x;
    const int total = SQ * NH * (DH / 2);
    if (idx >= total) return;
    const int d = idx % (DH / 2);
    const int t = idx / (DH / 2);
    const int h = t % NH;
    const int s = t / NH;

    const float c1 = cosp[s * DH + d];
    const float s1 = sinp[s * DH + d];
    const float c2 = cosp[s * DH + d + 36];
    const float s2 = sinp[s * DH + d + 36];

    size_t base = (size_t)s * QKV3 + h * DH;   // q
#pragma unroll
    for (int w = 0; w < 2; w++) {
        float x1 = qkv[base + d];
        float x2 = qkv[base + d + 36];
        qkv[base + d]      = x1 * c1 - x2 * s1;
        qkv[base + d + 36] = x2 * c2 + x1 * s2;
        base += DMODEL;                         // k
    }
}

// ---------------------------------------------------------------------------
// Flash attention, f32x2 GEMMs, register softmax state.
// BQ=64 rows, BK=64 key tile, 256 threads (16x16).
// GEMM1 microtile 4x4 (8 FFMA2), GEMM2 microtile 4x6 (12 FFMA2).
// smem (dynamic):
//   sQ2 [72][128]  Q duplicated (pre-scaled by 1/sqrt(DH))
//   sK  [72][66]   K transposed, pad 66
//   sV  [64][96]   V padded (cols 72..95 zero)
//   sS2 [64][132]  P duplicated, pad
// ---------------------------------------------------------------------------
#define BQ   64
#define BKT  64
#define SQ2_STRIDE 128
#define SK_STRIDE  66
#define SV_STRIDE  96
#define SS2_STRIDE 132

#define OFF_Q  0
#define OFF_K  (72 * SQ2_STRIDE)                 // 9216
#define OFF_V  (OFF_K + 72 * SK_STRIDE)          // 13968
#define OFF_S  (OFF_V + BKT * SV_STRIDE)         // 20112
#define ATTN_SMEM_FLOATS (OFF_S + BQ * SS2_STRIDE)   // 28560
#define ATTN_SMEM_BYTES  (ATTN_SMEM_FLOATS * 4)      // 114240

__global__ __launch_bounds__(256) void attn_kernel(
    const float* __restrict__ qkv, float* __restrict__ out)
{
    extern __shared__ float sm[];
    float* sQ2 = sm + OFF_Q;
    float* sK  = sm + OFF_K;
    float* sV  = sm + OFF_V;
    float* sS2 = sm + OFF_S;

    const int tid = threadIdx.x;
    const int qt = blockIdx.x;          // 0..15
    const int chh = blockIdx.y;         // 0..127
    const int chunk = chh >> 4, h = chh & 15;
    const size_t rowbase = (size_t)chunk * LCHUNK;
    const float* Qb = qkv + rowbase * QKV3 + h * DH;
    const float* Kb = Qb + DMODEL;
    const float* Vb = Qb + 2 * DMODEL;
    const int q0 = qt * BQ;

    const int ty = tid >> 4, tx = tid & 15;
    const int m0 = ty * 4;              // 4 q rows
    const int n0 = tx * 4;              // 4 score cols
    const int c0 = tx * 6;              // 6 output cols (of 96 padded)

    const float scl = rsqrtf((float)DH);

    // --- load Q duplicated + pre-scaled. 64 rows x 18 float4 ---
    for (int idx = tid; idx < BQ * 18; idx += 256) {
        const int m = idx & 63;
        const int q4 = idx >> 6;        // 0..17
        float4 qv = *(const float4*)&Qb[(size_t)(q0 + m) * QKV3 + 4 * q4];
        qv.x *= scl; qv.y *= scl; qv.z *= scl; qv.w *= scl;
        *(float2*)&sQ2[(4 * q4 + 0) * SQ2_STRIDE + 2 * m] = make_float2(qv.x, qv.x);
        *(float2*)&sQ2[(4 * q4 + 1) * SQ2_STRIDE + 2 * m] = make_float2(qv.y, qv.y);
        *(float2*)&sQ2[(4 * q4 + 2) * SQ2_STRIDE + 2 * m] = make_float2(qv.z, qv.z);
        *(float2*)&sQ2[(4 * q4 + 3) * SQ2_STRIDE + 2 * m] = make_float2(qv.w, qv.w);
    }
    // --- zero V pad columns (72..95), done once ---
    for (int idx = tid; idx < BKT * 24; idx += 256) {
        const int n = idx / 24, d = 72 + idx % 24;
        sV[n * SV_STRIDE + d] = 0.f;
    }

    ull acc[4][3];
#pragma unroll
    for (int i = 0; i < 4; i++)
#pragma unroll
        for (int j = 0; j < 3; j++) acc[i][j] = 0ULL;
    float mrow[4] = {-1e30f, -1e30f, -1e30f, -1e30f};
    float lrow[4] = {0.f, 0.f, 0.f, 0.f};

    for (int kt = 0; kt < LCHUNK / BKT; kt++) {
        const int k0 = kt * BKT;
        __syncthreads();   // previous GEMM2 readers done (also covers Q/Vpad on iter 0)

        // load K transposed: sK[d][n]
        for (int idx = tid; idx < BKT * DH; idx += 256) {
            const int d = idx % DH, n = idx / DH;
            sK[d * SK_STRIDE + n] = Kb[(size_t)(k0 + n) * QKV3 + d];
        }
        // load V: sV[n][d], d<72
        for (int idx = tid; idx < BKT * DH; idx += 256) {
            const int d = idx % DH, n = idx / DH;
            sV[n * SV_STRIDE + d] = Vb[(size_t)(k0 + n) * QKV3 + d];
        }
        __syncthreads();

        // --- GEMM1: S[4x4] = Q @ K^T via FFMA2 ---
        ull s2[4][2];
#pragma unroll
        for (int i = 0; i < 4; i++) { s2[i][0] = 0ULL; s2[i][1] = 0ULL; }
#pragma unroll 8
        for (int d = 0; d < DH; d++) {
            const ulonglong2* ap = (const ulonglong2*)&sQ2[d * SQ2_STRIDE + 2 * m0];
            ulonglong2 a01 = ap[0], a23 = ap[1];
            ull a2[4] = {a01.x, a01.y, a23.x, a23.y};
            ull b0 = *(const ull*)&sK[d * SK_STRIDE + n0];
            ull b1 = *(const ull*)&sK[d * SK_STRIDE + n0 + 2];
#pragma unroll
            for (int i = 0; i < 4; i++) {
                s2[i][0] = ffma2(a2[i], b0, s2[i][0]);
                s2[i][1] = ffma2(a2[i], b1, s2[i][1]);
            }
        }

        // --- online softmax (register state; half-warp row reductions) ---
#pragma unroll
        for (int i = 0; i < 4; i++) {
            float2 p01 = unpack2(s2[i][0]);
            float2 p23 = unpack2(s2[i][1]);
            float mx = fmaxf(fmaxf(p01.x, p01.y), fmaxf(p23.x, p23.y));
            mx = fmaxf(mx, __shfl_xor_sync(0xffffffffu, mx, 1));
            mx = fmaxf(mx, __shfl_xor_sync(0xffffffffu, mx, 2));
            mx = fmaxf(mx, __shfl_xor_sync(0xffffffffu, mx, 4));
            mx = fmaxf(mx, __shfl_xor_sync(0xffffffffu, mx, 8));
            const float mnew = fmaxf(mrow[i], mx);
            const float e0 = __expf(p01.x - mnew);
            const float e1 = __expf(p01.y - mnew);
            const float e2 = __expf(p23.x - mnew);
            const float e3 = __expf(p23.y - mnew);
            float ls = (e0 + e1) + (e2 + e3);
            ls += __shfl_xor_sync(0xffffffffu, ls, 1);
            ls += __shfl_xor_sync(0xffffffffu, ls, 2);
            ls += __shfl_xor_sync(0xffffffffu, ls, 4);
            ls += __shfl_xor_sync(0xffffffffu, ls, 8);
            const float sc = __expf(mrow[i] - mnew);
            lrow[i] = lrow[i] * sc + ls;
            mrow[i] = mnew;
            const ull sp = pack2(sc, sc);
            acc[i][0] = fmul2(acc[i][0], sp);
            acc[i][1] = fmul2(acc[i][1], sp);
            acc[i][2] = fmul2(acc[i][2], sp);
            // store P duplicated
            float* ps = &sS2[(m0 + i) * SS2_STRIDE + 2 * n0];
            *(float4*)(ps)     = make_float4(e0, e0, e1, e1);
            *(float4*)(ps + 4) = make_float4(e2, e2, e3, e3);
        }
        __syncwarp();   // P rows produced+consumed within this warp

        // --- GEMM2: O += P @ V via FFMA2 ---
#pragma unroll 4
        for (int kk = 0; kk < BKT; kk++) {
            ull p0 = *(const ull*)&sS2[(m0 + 0) * SS2_STRIDE + 2 * kk];
            ull p1 = *(const ull*)&sS2[(m0 + 1) * SS2_STRIDE + 2 * kk];
            ull p2 = *(const ull*)&sS2[(m0 + 2) * SS2_STRIDE + 2 * kk];
            ull p3 = *(const ull*)&sS2[(m0 + 3) * SS2_STRIDE + 2 * kk];
            const float* vrow = &sV[kk * SV_STRIDE + c0];
            ull v0 = *(const ull*)(vrow);
            ull v1 = *(const ull*)(vrow + 2);
            ull v2 = *(const ull*)(vrow + 4);
            acc[0][0] = ffma2(p0, v0, acc[0][0]);
            acc[0][1] = ffma2(p0, v1, acc[0][1]);
            acc[0][2] = ffma2(p0, v2, acc[0][2]);
            acc[1][0] = ffma2(p1, v0, acc[1][0]);
            acc[1][1] = ffma2(p1, v1, acc[1][1]);
            acc[1][2] = ffma2(p1, v2, acc[1][2]);
            acc[2][0] = ffma2(p2, v0, acc[2][0]);
            acc[2][1] = ffma2(p2, v1, acc[2][1]);
            acc[2][2] = ffma2(p2, v2, acc[2][2]);
            acc[3][0] = ffma2(p3, v0, acc[3][0]);
            acc[3][1] = ffma2(p3, v1, acc[3][1]);
            acc[3][2] = ffma2(p3, v2, acc[3][2]);
        }
    }

    // --- epilogue: normalize, store [S, H*DH] ---
    if (tx < 12) {
#pragma unroll
        for (int i = 0; i < 4; i++) {
            const float inv = 1.f / lrow[i];
            const size_t row = rowbase + q0 + m0 + i;
            float* op = out + row * DMODEL + h * DH + c0;
#pragma unroll
            for (int j = 0; j < 3; j++) {
                float2 f = unpack2(acc[i][j]);
                f.x *= inv; f.y *= inv;
                *(float2*)(op + 2 * j) = f;
            }
        }
    }
}

// ---------------------------------------------------------------------------
// kernel_launch
// ---------------------------------------------------------------------------
extern "C" void kernel_launch(void* const* d_in, const int* in_sizes, int n_in,
                              void* d_out, int out_size)
{
    const float* hidden = (const float*)d_in[0];
    const float* cosp   = (const float*)d_in[1];
    const float* sinp   = (const float*)d_in[2];
    const float* qkv_w  = (const float*)d_in[3];
    const float* qkv_b  = (const float*)d_in[4];
    const float* proj_w = (const float*)d_in[5];
    const float* proj_b = (const float*)d_in[6];
    (void)in_sizes; (void)n_in;

    float* qkv = nullptr;
    float* attn = nullptr;
    cudaGetSymbolAddress((void**)&qkv, g_qkv);
    cudaGetSymbolAddress((void**)&attn, g_attn);

    cudaFuncSetAttribute(attn_kernel,
                         cudaFuncAttributeMaxDynamicSharedMemorySize,
                         ATTN_SMEM_BYTES);

    // 1) QKV GEMM + bias
    sgemm_bias_kernel<<<dim3(QKV3 / GBN, SQ / GBM), 256>>>(
        hidden, qkv_w, qkv_b, qkv, SQ, QKV3, DMODEL);

    // 2) RoPE
    {
        const int total = SQ * NH * (DH / 2);
        rope_kernel<<<(total + 255) / 256, 256>>>(qkv, cosp, sinp);
    }

    // 3) attention
    attn_kernel<<<dim3(LCHUNK / BQ, NCHUNK * NH), 256, ATTN_SMEM_BYTES>>>(qkv, attn);

    // 4) output projection + bias
    sgemm_bias_kernel<<<dim3(DMODEL / GBN, SQ / GBM), 256>>>(
        attn, proj_w, proj_b, (float*)d_out, SQ, DMODEL, DMODEL);
}

// round 4
// speedup vs baseline: 1.9843x; 1.9843x over previous
#include <cuda_runtime.h>
#include <cuda_fp16.h>
#include <cstdint>

// Problem constants
#define SQ     8192
#define DMODEL 1152
#define NH     16
#define DH     72
#define QKV3   3456
#define LCHUNK 1024
#define NCHUNK 8

// Scratch (device globals; no cudaMalloc allowed)
__device__ float  g_qkv[(size_t)SQ * QKV3];        // fp32 [S, 3, H, DH]
__device__ __half g_hidden_h[(size_t)SQ * DMODEL]; // fp16 hidden
__device__ __half g_qkvw_h[(size_t)QKV3 * DMODEL]; // fp16 qkv weight
__device__ __half g_projw_h[(size_t)DMODEL * DMODEL];
__device__ __half g_attn_h[(size_t)SQ * DMODEL];   // fp16 attention output

// ---------------------------------------------------------------------------
// fp32 -> fp16 conversion (vectorized, n % 4 == 0)
// ---------------------------------------------------------------------------
__global__ __launch_bounds__(256) void cvt_f16_kernel(
    const float* __restrict__ in, __half* __restrict__ out, int n)
{
    const int i = (blockIdx.x * blockDim.x + threadIdx.x) * 4;
    if (i >= n) return;
    const float4 v = *(const float4*)(in + i);
    __half2* o = (__half2*)(out + i);
    o[0] = __floats2half2_rn(v.x, v.y);
    o[1] = __floats2half2_rn(v.z, v.w);
}

// ---------------------------------------------------------------------------
// fp16 tensor-core GEMM via mma.sync (baseline PTX, works on plain sm_103):
//   C[M,N] = A[M,K] @ W[N,K]^T + bias[N]    (A, W fp16 K-major; C fp32)
// 128x128 block tile, BK=32, 256 threads (8 warps, 2x4 grid, 64x32 per warp).
// cp.async double-buffered smem, 80B padded rows (conflict-free ldmatrix).
// ---------------------------------------------------------------------------
#define BM 128
#define BN 128
#define BK 32
#define SROW 80   // padded smem row stride in bytes (32 fp16 = 64B data)

__device__ __forceinline__ uint32_t smem_u32(const void* p) {
    uint32_t a;
    asm("{ .reg .u64 t; cvta.to.shared.u64 t, %1; cvt.u32.u64 %0, t; }"
        : "=r"(a) : "l"(p));
    return a;
}
__device__ __forceinline__ void cp16(uint32_t dst, const void* src) {
    asm volatile("cp.async.ca.shared.global [%0], [%1], 16;"
                 :: "r"(dst), "l"(src));
}
__device__ __forceinline__ void cp_commit() {
    asm volatile("cp.async.commit_group;");
}
__device__ __forceinline__ void cp_wait0() {
    asm volatile("cp.async.wait_group 0;");
}
__device__ __forceinline__ void ldmatrix4(uint32_t& r0, uint32_t& r1,
                                          uint32_t& r2, uint32_t& r3,
                                          uint32_t addr) {
    asm volatile("ldmatrix.sync.aligned.m8n8.x4.shared.b16 {%0,%1,%2,%3}, [%4];"
                 : "=r"(r0), "=r"(r1), "=r"(r2), "=r"(r3) : "r"(addr));
}
__device__ __forceinline__ void mma16816(float& c0, float& c1, float& c2, float& c3,
                                         uint32_t a0, uint32_t a1, uint32_t a2, uint32_t a3,
                                         uint32_t b0, uint32_t b1) {
    asm volatile(
        "mma.sync.aligned.m16n8k16.row.col.f32.f16.f16.f32 "
        "{%0,%1,%2,%3}, {%4,%5,%6,%7}, {%8,%9}, {%0,%1,%2,%3};"
        : "+f"(c0), "+f"(c1), "+f"(c2), "+f"(c3)
        : "r"(a0), "r"(a1), "r"(a2), "r"(a3), "r"(b0), "r"(b1));
}

__global__ __launch_bounds__(256) void gemm_f16_kernel(
    const __half* __restrict__ A, const __half* __restrict__ W,
    const float* __restrict__ bias, float* __restrict__ C,
    int M, int N, int K)
{
    __shared__ __align__(16) unsigned char As[2][BM * SROW];
    __shared__ __align__(16) unsigned char Bs[2][BN * SROW];

    const int tid  = threadIdx.x;
    const int wid  = tid >> 5;
    const int lane = tid & 31;
    const int bm = blockIdx.y * BM;
    const int bn = blockIdx.x * BN;

    const int warp_m = (wid >> 2) * 64;   // 0 or 64
    const int warp_n = (wid & 3) * 32;    // 0,32,64,96

    const uint32_t sA = smem_u32(As);
    const uint32_t sB = smem_u32(Bs);

    // loader mapping: 512 16B-chunks per matrix per stage; 2 per thread
    const int c0r = tid >> 2, c0k = tid & 3;             // chunk tid
    const int c1r = (tid + 256) >> 2, c1k = tid & 3;     // chunk tid+256

    const int nslab = K / BK;   // 36

    // ---- prologue: load slab 0 ----
    {
        const __half* Ag = A + (size_t)(bm + c0r) * K + c0k * 8;
        const __half* Wg = W + (size_t)(bn + c0r) * K + c0k * 8;
        cp16(sA + c0r * SROW + c0k * 16, Ag);
        cp16(sB + c0r * SROW + c0k * 16, Wg);
        const __half* Ag1 = A + (size_t)(bm + c1r) * K + c1k * 8;
        const __half* Wg1 = W + (size_t)(bn + c1r) * K + c1k * 8;
        cp16(sA + c1r * SROW + c1k * 16, Ag1);
        cp16(sB + c1r * SROW + c1k * 16, Wg1);
        cp_commit();
    }

    float acc[4][4][4];
#pragma unroll
    for (int i = 0; i < 4; i++)
#pragma unroll
        for (int j = 0; j < 4; j++)
#pragma unroll
            for (int v = 0; v < 4; v++) acc[i][j][v] = 0.f;

    // ldmatrix per-lane address components
    const int a_row = lane & 15;            // m offset within 16
    const int a_kof = (lane >> 4) * 8;      // k offset 0/8
    const int b_row = ((lane >> 4) * 8) + (lane & 7);  // n offset within 16
    const int b_kof = ((lane >> 3) & 1) * 8;           // k offset 0/8

    for (int s = 0; s < nslab; s++) {
        const int buf = s & 1;
        cp_wait0();
        __syncthreads();

        if (s + 1 < nslab) {
            const int nbuf = (s + 1) & 1;
            const int k0 = (s + 1) * BK;
            const __half* Ag = A + (size_t)(bm + c0r) * K + k0 + c0k * 8;
            const __half* Wg = W + (size_t)(bn + c0r) * K + k0 + c0k * 8;
            cp16(sA + nbuf * (BM * SROW) + c0r * SROW + c0k * 16, Ag);
            cp16(sB + nbuf * (BN * SROW) + c0r * SROW + c0k * 16, Wg);
            const __half* Ag1 = A + (size_t)(bm + c1r) * K + k0 + c1k * 8;
            const __half* Wg1 = W + (size_t)(bn + c1r) * K + k0 + c1k * 8;
            cp16(sA + nbuf * (BM * SROW) + c1r * SROW + c1k * 16, Ag1);
            cp16(sB + nbuf * (BN * SROW) + c1r * SROW + c1k * 16, Wg1);
            cp_commit();
        }

        const uint32_t bA = sA + buf * (BM * SROW);
        const uint32_t bB = sB + buf * (BN * SROW);

#pragma unroll
        for (int ks = 0; ks < 2; ks++) {          // two k16 steps per slab
            // A fragments: 4 m16 tiles
            uint32_t af[4][4];
#pragma unroll
            for (int mt = 0; mt < 4; mt++) {
                const uint32_t addr = bA
                    + (warp_m + mt * 16 + a_row) * SROW
                    + (ks * 16 + a_kof) * 2;
                ldmatrix4(af[mt][0], af[mt][1], af[mt][2], af[mt][3], addr);
            }
            // B fragments: 4 n8 tiles via 2x ldmatrix.x4
            uint32_t bf[4][2];
#pragma unroll
            for (int nt2 = 0; nt2 < 2; nt2++) {
                uint32_t r0, r1, r2, r3;
                const uint32_t addr = bB
                    + (warp_n + nt2 * 16 + b_row) * SROW
                    + (ks * 16 + b_kof) * 2;
                ldmatrix4(r0, r1, r2, r3, addr);
                bf[nt2 * 2 + 0][0] = r0; bf[nt2 * 2 + 0][1] = r1;
                bf[nt2 * 2 + 1][0] = r2; bf[nt2 * 2 + 1][1] = r3;
            }
#pragma unroll
            for (int mt = 0; mt < 4; mt++)
#pragma unroll
                for (int nt = 0; nt < 4; nt++)
                    mma16816(acc[mt][nt][0], acc[mt][nt][1],
                             acc[mt][nt][2], acc[mt][nt][3],
                             af[mt][0], af[mt][1], af[mt][2], af[mt][3],
                             bf[nt][0], bf[nt][1]);
        }
        __syncthreads();
    }

    // ---- epilogue: bias + fp32 store ----
    const int erow = lane >> 2;          // 0..7
    const int ecol = (lane & 3) * 2;
#pragma unroll
    for (int mt = 0; mt < 4; mt++) {
#pragma unroll
        for (int nt = 0; nt < 4; nt++) {
            const int col = bn + warp_n + nt * 8 + ecol;
            const float b0 = bias[col], b1 = bias[col + 1];
            const size_t r0 = (size_t)(bm + warp_m + mt * 16 + erow);
            float2 o0 = make_float2(acc[mt][nt][0] + b0, acc[mt][nt][1] + b1);
            float2 o1 = make_float2(acc[mt][nt][2] + b0, acc[mt][nt][3] + b1);
            *(float2*)(C + r0 * N + col)       = o0;
            *(float2*)(C + (r0 + 8) * N + col) = o1;
        }
    }
}

// ---------------------------------------------------------------------------
// RoPE on q and k in-place inside g_qkv. Layout [S, 3, H, DH].
// ---------------------------------------------------------------------------
__global__ __launch_bounds__(256) void rope_kernel(
    float* __restrict__ qkv, const float* __restrict__ cosp,
    const float* __restrict__ sinp)
{
    const int idx = blockIdx.x * blockDim.x + threadIdx.x;
    const int total = SQ * NH * (DH / 2);
    if (idx >= total) return;
    const int d = idx % (DH / 2);
    const int t = idx / (DH / 2);
    const int h = t % NH;
    const int s = t / NH;

    const float c1 = cosp[s * DH + d];
    const float s1 = sinp[s * DH + d];
    const float c2 = cosp[s * DH + d + 36];
    const float s2 = sinp[s * DH + d + 36];

    size_t base = (size_t)s * QKV3 + h * DH;   // q
#pragma unroll
    for (int w = 0; w < 2; w++) {
        float x1 = qkv[base + d];
        float x2 = qkv[base + d + 36];
        qkv[base + d]      = x1 * c1 - x2 * s1;
        qkv[base + d + 36] = x2 * c2 + x1 * s2;
        base += DMODEL;                         // k
    }
}

// ---------------------------------------------------------------------------
// Flash-style attention (known-good R1), writes fp16 output for proj GEMM.
// ---------------------------------------------------------------------------
#define BQ  64
#define BKT 32
#define DHP 80

__global__ __launch_bounds__(256) void attn_kernel(
    const float* __restrict__ qkv, __half* __restrict__ out)
{
    __shared__ float sQ[DH][BQ];
    __shared__ float sK[DH][BKT];
    __shared__ float sV[BKT][DHP];
    __shared__ float sS[BQ][34];
    __shared__ float sM[BQ], sL[BQ], sScale[BQ];

    const int tid = threadIdx.x;
    const int qt = blockIdx.x;
    const int chh = blockIdx.y;
    const int chunk = chh >> 4, h = chh & 15;
    const size_t rowbase = (size_t)chunk * LCHUNK;
    const float* Qb = qkv + rowbase * QKV3 + h * DH;
    const float* Kb = Qb + DMODEL;
    const float* Vb = Qb + 2 * DMODEL;
    const int q0 = qt * BQ;

    for (int idx = tid; idx < BQ * DH; idx += 256) {
        const int m = idx / DH, d = idx - m * DH;
        sQ[d][m] = Qb[(size_t)(q0 + m) * QKV3 + d];
    }
    if (tid < BQ) { sM[tid] = -1e30f; sL[tid] = 0.f; }

    const int ty = tid >> 4, tx = tid & 15;
    const int m0 = ty * 4;
    const int n0 = tx * 2;
    const int c0 = tx * 5;

    float acc[4][5];
#pragma unroll
    for (int i = 0; i < 4; i++)
#pragma unroll
        for (int j = 0; j < 5; j++) acc[i][j] = 0.f;

    const float scl = rsqrtf((float)DH);
    __syncthreads();

    for (int kt = 0; kt < LCHUNK / BKT; kt++) {
        const int k0 = kt * BKT;
        for (int idx = tid; idx < BKT * DH; idx += 256) {
            const int n = idx / DH, d = idx - n * DH;
            sK[d][n] = Kb[(size_t)(k0 + n) * QKV3 + d];
        }
        for (int idx = tid; idx < BKT * DHP; idx += 256) {
            const int n = idx / DHP, d = idx - n * DHP;
            sV[n][d] = (d < DH) ? Vb[(size_t)(k0 + n) * QKV3 + d] : 0.f;
        }
        __syncthreads();

        float sa00 = 0.f, sa01 = 0.f, sa10 = 0.f, sa11 = 0.f;
        float sa20 = 0.f, sa21 = 0.f, sa30 = 0.f, sa31 = 0.f;
#pragma unroll
        for (int d = 0; d < DH; d++) {
            const float4 a = *(const float4*)&sQ[d][m0];
            const float2 b = *(const float2*)&sK[d][n0];
            sa00 += a.x * b.x; sa01 += a.x * b.y;
            sa10 += a.y * b.x; sa11 += a.y * b.y;
            sa20 += a.z * b.x; sa21 += a.z * b.y;
            sa30 += a.w * b.x; sa31 += a.w * b.y;
        }
        sS[m0 + 0][n0] = sa00 * scl; sS[m0 + 0][n0 + 1] = sa01 * scl;
        sS[m0 + 1][n0] = sa10 * scl; sS[m0 + 1][n0 + 1] = sa11 * scl;
        sS[m0 + 2][n0] = sa20 * scl; sS[m0 + 2][n0 + 1] = sa21 * scl;
        sS[m0 + 3][n0] = sa30 * scl; sS[m0 + 3][n0 + 1] = sa31 * scl;
        __syncthreads();

        {
            const int r = tid >> 2, part = tid & 3;
            float vals[8];
            float mloc = -1e30f;
#pragma unroll
            for (int u = 0; u < 8; u++) {
                vals[u] = sS[r][part * 8 + u];
                mloc = fmaxf(mloc, vals[u]);
            }
            mloc = fmaxf(mloc, __shfl_xor_sync(0xffffffffu, mloc, 1));
            mloc = fmaxf(mloc, __shfl_xor_sync(0xffffffffu, mloc, 2));
            const float mold = sM[r];
            const float mnew = fmaxf(mold, mloc);
            float lsum = 0.f;
#pragma unroll
            for (int u = 0; u < 8; u++) {
                const float p = __expf(vals[u] - mnew);
                sS[r][part * 8 + u] = p;
                lsum += p;
            }
            lsum += __shfl_xor_sync(0xffffffffu, lsum, 1);
            lsum += __shfl_xor_sync(0xffffffffu, lsum, 2);
            if (part == 0) {
                const float sc = __expf(mold - mnew);
                sScale[r] = sc;
                sM[r] = mnew;
                sL[r] = sL[r] * sc + lsum;
            }
        }
        __syncthreads();

#pragma unroll
        for (int i = 0; i < 4; i++) {
            const float sc = sScale[m0 + i];
#pragma unroll
            for (int j = 0; j < 5; j++) acc[i][j] *= sc;
        }
#pragma unroll
        for (int kk = 0; kk < BKT; kk++) {
            const float p0 = sS[m0 + 0][kk];
            const float p1 = sS[m0 + 1][kk];
            const float p2 = sS[m0 + 2][kk];
            const float p3 = sS[m0 + 3][kk];
#pragma unroll
            for (int j = 0; j < 5; j++) {
                const float v = sV[kk][c0 + j];
                acc[0][j] += p0 * v;
                acc[1][j] += p1 * v;
                acc[2][j] += p2 * v;
                acc[3][j] += p3 * v;
            }
        }
        __syncthreads();
    }

#pragma unroll
    for (int i = 0; i < 4; i++) {
        const float inv = 1.f / sL[m0 + i];
        const size_t row = rowbase + q0 + m0 + i;
#pragma unroll
        for (int j = 0; j < 5; j++) {
            const int d = c0 + j;
            if (d < DH)
                out[row * DMODEL + h * DH + d] = __float2half_rn(acc[i][j] * inv);
        }
    }
}

// ---------------------------------------------------------------------------
// kernel_launch
// ---------------------------------------------------------------------------
extern "C" void kernel_launch(void* const* d_in, const int* in_sizes, int n_in,
                              void* d_out, int out_size)
{
    const float* hidden = (const float*)d_in[0];
    const float* cosp   = (const float*)d_in[1];
    const float* sinp   = (const float*)d_in[2];
    const float* qkv_w  = (const float*)d_in[3];
    const float* qkv_b  = (const float*)d_in[4];
    const float* proj_w = (const float*)d_in[5];
    const float* proj_b = (const float*)d_in[6];
    (void)in_sizes; (void)n_in;

    float*  qkv = nullptr;
    __half* hidden_h = nullptr;
    __half* qkvw_h = nullptr;
    __half* projw_h = nullptr;
    __half* attn_h = nullptr;
    cudaGetSymbolAddress((void**)&qkv, g_qkv);
    cudaGetSymbolAddress((void**)&hidden_h, g_hidden_h);
    cudaGetSymbolAddress((void**)&qkvw_h, g_qkvw_h);
    cudaGetSymbolAddress((void**)&projw_h, g_projw_h);
    cudaGetSymbolAddress((void**)&attn_h, g_attn_h);

    // 0) fp32 -> fp16 conversions
    {
        const int n1 = SQ * DMODEL;
        cvt_f16_kernel<<<(n1 / 4 + 255) / 256, 256>>>(hidden, hidden_h, n1);
        const int n2 = QKV3 * DMODEL;
        cvt_f16_kernel<<<(n2 / 4 + 255) / 256, 256>>>(qkv_w, qkvw_h, n2);
        const int n3 = DMODEL * DMODEL;
        cvt_f16_kernel<<<(n3 / 4 + 255) / 256, 256>>>(proj_w, projw_h, n3);
    }

    // 1) QKV GEMM + bias  (tensor cores via mma.sync)
    gemm_f16_kernel<<<dim3(QKV3 / BN, SQ / BM), 256>>>(
        hidden_h, qkvw_h, qkv_b, qkv, SQ, QKV3, DMODEL);

    // 2) RoPE (fp32)
    {
        const int total = SQ * NH * (DH / 2);
        rope_kernel<<<(total + 255) / 256, 256>>>(qkv, cosp, sinp);
    }

    // 3) attention (scalar flash, fp32 math, fp16 output)
    attn_kernel<<<dim3(LCHUNK / BQ, NCHUNK * NH), 256>>>(qkv, attn_h);

    // 4) output projection + bias (tensor cores)
    gemm_f16_kernel<<<dim3(DMODEL / BN, SQ / BM), 256>>>(
        attn_h, projw_h, proj_b, (float*)d_out, SQ, DMODEL, DMODEL);
}

// round 5
// speedup vs baseline: 6.9692x; 3.5121x over previous
#include <cuda_runtime.h>
#include <cuda_fp16.h>
#include <cstdint>

// Problem constants
#define SQ     8192
#define DMODEL 1152
#define NH     16
#define DH     72
#define QKV3   3456
#define LCHUNK 1024
#define NCHUNK 8

// Scratch (device globals; no cudaMalloc allowed)
__device__ float  g_qkv[(size_t)SQ * QKV3];        // fp32 qkv GEMM output
__device__ __half g_hidden_h[(size_t)SQ * DMODEL];
__device__ __half g_qkvw_h[(size_t)QKV3 * DMODEL];
__device__ __half g_projw_h[(size_t)DMODEL * DMODEL];
__device__ __half g_q_h[(size_t)SQ * DMODEL];      // roped+scaled Q fp16
__device__ __half g_k_h[(size_t)SQ * DMODEL];      // roped K fp16
__device__ __half g_vt[(size_t)NCHUNK * NH * DH * LCHUNK];  // V^T per (chunk,head)
__device__ __half g_attn_h[(size_t)SQ * DMODEL];   // attention output fp16

// ---------------------------------------------------------------------------
// common PTX helpers
// ---------------------------------------------------------------------------
__device__ __forceinline__ uint32_t smem_u32(const void* p) {
    uint32_t a;
    asm("{ .reg .u64 t; cvta.to.shared.u64 t, %1; cvt.u32.u64 %0, t; }"
        : "=r"(a) : "l"(p));
    return a;
}
__device__ __forceinline__ void cp16(uint32_t dst, const void* src) {
    asm volatile("cp.async.ca.shared.global [%0], [%1], 16;"
                 :: "r"(dst), "l"(src));
}
__device__ __forceinline__ void cp_commit() {
    asm volatile("cp.async.commit_group;");
}
template <int N>
__device__ __forceinline__ void cp_wait() {
    asm volatile("cp.async.wait_group %0;" :: "n"(N));
}
__device__ __forceinline__ void ldmatrix4(uint32_t& r0, uint32_t& r1,
                                          uint32_t& r2, uint32_t& r3,
                                          uint32_t addr) {
    asm volatile("ldmatrix.sync.aligned.m8n8.x4.shared.b16 {%0,%1,%2,%3}, [%4];"
                 : "=r"(r0), "=r"(r1), "=r"(r2), "=r"(r3) : "r"(addr));
}
__device__ __forceinline__ void mma16816(float& c0, float& c1, float& c2, float& c3,
                                         uint32_t a0, uint32_t a1, uint32_t a2, uint32_t a3,
                                         uint32_t b0, uint32_t b1) {
    asm volatile(
        "mma.sync.aligned.m16n8k16.row.col.f32.f16.f16.f32 "
        "{%0,%1,%2,%3}, {%4,%5,%6,%7}, {%8,%9}, {%0,%1,%2,%3};"
        : "+f"(c0), "+f"(c1), "+f"(c2), "+f"(c3)
        : "r"(a0), "r"(a1), "r"(a2), "r"(a3), "r"(b0), "r"(b1));
}
__device__ __forceinline__ uint32_t pack_h2(float lo, float hi) {
    uint32_t r;
    asm("cvt.rn.f16x2.f32 %0, %1, %2;" : "=r"(r) : "f"(hi), "f"(lo));
    return r;
}

// ---------------------------------------------------------------------------
// fp32 -> fp16 conversion
// ---------------------------------------------------------------------------
__global__ __launch_bounds__(256) void cvt_f16_kernel(
    const float* __restrict__ in, __half* __restrict__ out, int n)
{
    const int i = (blockIdx.x * blockDim.x + threadIdx.x) * 4;
    if (i >= n) return;
    const float4 v = *(const float4*)(in + i);
    __half2* o = (__half2*)(out + i);
    o[0] = __floats2half2_rn(v.x, v.y);
    o[1] = __floats2half2_rn(v.z, v.w);
}

// ---------------------------------------------------------------------------
// fp16 tensor-core GEMM (R4, unchanged): C = A @ W^T + bias
// ---------------------------------------------------------------------------
#define BM 128
#define BN 128
#define BK 32
#define SROW 80

__global__ __launch_bounds__(256) void gemm_f16_kernel(
    const __half* __restrict__ A, const __half* __restrict__ W,
    const float* __restrict__ bias, float* __restrict__ C,
    int M, int N, int K)
{
    __shared__ __align__(16) unsigned char As[2][BM * SROW];
    __shared__ __align__(16) unsigned char Bs[2][BN * SROW];

    const int tid  = threadIdx.x;
    const int wid  = tid >> 5;
    const int lane = tid & 31;
    const int bm = blockIdx.y * BM;
    const int bn = blockIdx.x * BN;

    const int warp_m = (wid >> 2) * 64;
    const int warp_n = (wid & 3) * 32;

    const uint32_t sA = smem_u32(As);
    const uint32_t sB = smem_u32(Bs);

    const int c0r = tid >> 2, c0k = tid & 3;
    const int c1r = (tid + 256) >> 2, c1k = tid & 3;

    const int nslab = K / BK;

    {
        cp16(sA + c0r * SROW + c0k * 16, A + (size_t)(bm + c0r) * K + c0k * 8);
        cp16(sB + c0r * SROW + c0k * 16, W + (size_t)(bn + c0r) * K + c0k * 8);
        cp16(sA + c1r * SROW + c1k * 16, A + (size_t)(bm + c1r) * K + c1k * 8);
        cp16(sB + c1r * SROW + c1k * 16, W + (size_t)(bn + c1r) * K + c1k * 8);
        cp_commit();
    }

    float acc[4][4][4];
#pragma unroll
    for (int i = 0; i < 4; i++)
#pragma unroll
        for (int j = 0; j < 4; j++)
#pragma unroll
            for (int v = 0; v < 4; v++) acc[i][j][v] = 0.f;

    const int a_row = lane & 15;
    const int a_kof = (lane >> 4) * 8;
    const int b_row = ((lane >> 4) * 8) + (lane & 7);
    const int b_kof = ((lane >> 3) & 1) * 8;

    for (int s = 0; s < nslab; s++) {
        const int buf = s & 1;
        cp_wait<0>();
        __syncthreads();

        if (s + 1 < nslab) {
            const int nbuf = (s + 1) & 1;
            const int k0 = (s + 1) * BK;
            cp16(sA + nbuf * (BM * SROW) + c0r * SROW + c0k * 16,
                 A + (size_t)(bm + c0r) * K + k0 + c0k * 8);
            cp16(sB + nbuf * (BN * SROW) + c0r * SROW + c0k * 16,
                 W + (size_t)(bn + c0r) * K + k0 + c0k * 8);
            cp16(sA + nbuf * (BM * SROW) + c1r * SROW + c1k * 16,
                 A + (size_t)(bm + c1r) * K + k0 + c1k * 8);
            cp16(sB + nbuf * (BN * SROW) + c1r * SROW + c1k * 16,
                 W + (size_t)(bn + c1r) * K + k0 + c1k * 8);
            cp_commit();
        }

        const uint32_t bA = sA + buf * (BM * SROW);
        const uint32_t bB = sB + buf * (BN * SROW);

#pragma unroll
        for (int ks = 0; ks < 2; ks++) {
            uint32_t af[4][4];
#pragma unroll
            for (int mt = 0; mt < 4; mt++) {
                const uint32_t addr = bA
                    + (warp_m + mt * 16 + a_row) * SROW
                    + (ks * 16 + a_kof) * 2;
                ldmatrix4(af[mt][0], af[mt][1], af[mt][2], af[mt][3], addr);
            }
            uint32_t bf[4][2];
#pragma unroll
            for (int nt2 = 0; nt2 < 2; nt2++) {
                uint32_t r0, r1, r2, r3;
                const uint32_t addr = bB
                    + (warp_n + nt2 * 16 + b_row) * SROW
                    + (ks * 16 + b_kof) * 2;
                ldmatrix4(r0, r1, r2, r3, addr);
                bf[nt2 * 2 + 0][0] = r0; bf[nt2 * 2 + 0][1] = r1;
                bf[nt2 * 2 + 1][0] = r2; bf[nt2 * 2 + 1][1] = r3;
            }
#pragma unroll
            for (int mt = 0; mt < 4; mt++)
#pragma unroll
                for (int nt = 0; nt < 4; nt++)
                    mma16816(acc[mt][nt][0], acc[mt][nt][1],
                             acc[mt][nt][2], acc[mt][nt][3],
                             af[mt][0], af[mt][1], af[mt][2], af[mt][3],
                             bf[nt][0], bf[nt][1]);
        }
        __syncthreads();
    }

    const int erow = lane >> 2;
    const int ecol = (lane & 3) * 2;
#pragma unroll
    for (int mt = 0; mt < 4; mt++) {
#pragma unroll
        for (int nt = 0; nt < 4; nt++) {
            const int col = bn + warp_n + nt * 8 + ecol;
            const float b0 = bias[col], b1 = bias[col + 1];
            const size_t r0 = (size_t)(bm + warp_m + mt * 16 + erow);
            *(float2*)(C + r0 * N + col) =
                make_float2(acc[mt][nt][0] + b0, acc[mt][nt][1] + b1);
            *(float2*)(C + (r0 + 8) * N + col) =
                make_float2(acc[mt][nt][2] + b0, acc[mt][nt][3] + b1);
        }
    }
}

// ---------------------------------------------------------------------------
// RoPE + pack: fp32 qkv -> fp16 Q (pre-scaled), fp16 K, fp16 V^T
// ---------------------------------------------------------------------------
__global__ __launch_bounds__(256) void rope_pack_kernel(
    const float* __restrict__ qkv, const float* __restrict__ cosp,
    const float* __restrict__ sinp,
    __half* __restrict__ qh, __half* __restrict__ kh, __half* __restrict__ vt)
{
    const int idx = blockIdx.x * blockDim.x + threadIdx.x;
    const int total = SQ * NH * (DH / 2);
    if (idx >= total) return;
    const int d = idx % (DH / 2);
    const int t = idx / (DH / 2);
    const int h = t % NH;
    const int s = t / NH;

    const float c1 = cosp[s * DH + d];
    const float s1 = sinp[s * DH + d];
    const float c2 = cosp[s * DH + d + 36];
    const float s2 = sinp[s * DH + d + 36];
    const float scl = rsqrtf((float)DH);

    const size_t base = (size_t)s * QKV3 + h * DH;
    // q (scaled)
    {
        const float x1 = qkv[base + d];
        const float x2 = qkv[base + d + 36];
        qh[(size_t)s * DMODEL + h * DH + d]      = __float2half_rn((x1 * c1 - x2 * s1) * scl);
        qh[(size_t)s * DMODEL + h * DH + d + 36] = __float2half_rn((x2 * c2 + x1 * s2) * scl);
    }
    // k
    {
        const float x1 = qkv[base + DMODEL + d];
        const float x2 = qkv[base + DMODEL + d + 36];
        kh[(size_t)s * DMODEL + h * DH + d]      = __float2half_rn(x1 * c1 - x2 * s1);
        kh[(size_t)s * DMODEL + h * DH + d + 36] = __float2half_rn(x2 * c2 + x1 * s2);
    }
    // v transposed: vt[(chunk*NH+h)*DH*L + d*L + slocal]
    {
        const int chunk = s >> 10, sl = s & 1023;
        const size_t vb = ((size_t)(chunk * NH + h) * DH) * LCHUNK + sl;
        vt[vb + (size_t)d * LCHUNK]        = __float2half_rn(qkv[base + 2 * DMODEL + d]);
        vt[vb + (size_t)(d + 36) * LCHUNK] = __float2half_rn(qkv[base + 2 * DMODEL + d + 36]);
    }
}

// ---------------------------------------------------------------------------
// Tensor-core flash attention.
// Block: 128 q rows x (chunk,head). 8 warps, m16 per warp. Key tiles of 64,
// double-buffered cp.async. dh padded 72->80 (zeroed pads).
// smem strides: 176B (sQ,sK rows), 144B (sVt rows) -> conflict-free ldmatrix.
// ---------------------------------------------------------------------------
#define AQ_ROWB  176
#define AVT_ROWB 144
#define A_SQ_OFF  0
#define A_SK_OFF  (128 * AQ_ROWB)                 // 22528
#define A_SK_SZ   (64 * AQ_ROWB)                  // 11264
#define A_SVT_OFF (A_SK_OFF + 2 * A_SK_SZ)        // 45056
#define A_SVT_SZ  (80 * AVT_ROWB)                 // 11520
#define A_SMEM_BYTES (A_SVT_OFF + 2 * A_SVT_SZ)   // 68096

__global__ __launch_bounds__(256) void attn_mma_kernel(
    const __half* __restrict__ Qg, const __half* __restrict__ Kg,
    const __half* __restrict__ Vtg, __half* __restrict__ out)
{
    extern __shared__ unsigned char asmem[];
    const uint32_t sb = smem_u32(asmem);
    const int tid  = threadIdx.x;
    const int wid  = tid >> 5;
    const int lane = tid & 31;
    const int qt  = blockIdx.x;      // 0..7
    const int chh = blockIdx.y;      // 0..127  (chunk*16 + head)
    const int chunk = chh >> 4, h = chh & 15;
    const size_t rowbase = (size_t)chunk * LCHUNK;
    const int q0 = qt * 128;
    const int warp_m = wid * 16;

    // ---- zero pads (sQ cols 72..79, sK cols 72..79 both bufs, sVt rows 72..79) ----
    const uint4 z4 = make_uint4(0, 0, 0, 0);
    if (tid < 128)
        *(uint4*)(asmem + A_SQ_OFF + tid * AQ_ROWB + 144) = z4;
    else {
        const int t = tid - 128;
        *(uint4*)(asmem + A_SK_OFF + (t >> 6) * A_SK_SZ + (t & 63) * AQ_ROWB + 144) = z4;
    }
    for (int i = tid; i < 144; i += 256) {
        const int buf = i / 72, rem = i % 72;
        const int row = 72 + rem / 9, c = rem % 9;
        *(uint4*)(asmem + A_SVT_OFF + buf * A_SVT_SZ + row * AVT_ROWB + c * 16) = z4;
    }

    // ---- cp.async: Q tile (128 rows x 9 chunks) + key tile 0 ----
    for (int i = tid; i < 128 * 9; i += 256) {
        const int row = i / 9, c = i % 9;
        cp16(sb + A_SQ_OFF + row * AQ_ROWB + c * 16,
             Qg + (rowbase + q0 + row) * DMODEL + h * DH + c * 8);
    }
    {
        for (int i = tid; i < 1152; i += 256) {
            if (i < 576) {
                const int row = i / 9, c = i % 9;
                cp16(sb + A_SK_OFF + row * AQ_ROWB + c * 16,
                     Kg + (rowbase + row) * DMODEL + h * DH + c * 8);
            } else {
                const int j = i - 576;
                const int d = j / 8, c = j % 8;
                cp16(sb + A_SVT_OFF + d * AVT_ROWB + c * 16,
                     Vtg + ((size_t)chh * DH + d) * LCHUNK + c * 8);
            }
        }
        cp_commit();
    }

    // fragment addressing
    const int a_row = lane & 15;
    const int a_kof = (lane >> 4) * 8;
    const int b_row = ((lane >> 4) * 8) + (lane & 7);
    const int b_kof = ((lane >> 3) & 1) * 8;

    uint32_t qf[5][4];          // Q fragments (loaded after first sync)
    float oacc[9][4];
#pragma unroll
    for (int i = 0; i < 9; i++)
#pragma unroll
        for (int j = 0; j < 4; j++) oacc[i][j] = 0.f;
    float m0 = -1e30f, m1 = -1e30f, l0 = 0.f, l1 = 0.f;

    const int NTILE = LCHUNK / 64;   // 16

    for (int t = 0; t < NTILE; t++) {
        const int buf = t & 1;
        // prefetch next tile
        if (t + 1 < NTILE) {
            const int nbuf = (t + 1) & 1;
            const int k0 = (t + 1) * 64;
            for (int i = tid; i < 1152; i += 256) {
                if (i < 576) {
                    const int row = i / 9, c = i % 9;
                    cp16(sb + A_SK_OFF + nbuf * A_SK_SZ + row * AQ_ROWB + c * 16,
                         Kg + (rowbase + k0 + row) * DMODEL + h * DH + c * 8);
                } else {
                    const int j = i - 576;
                    const int d = j / 8, c = j % 8;
                    cp16(sb + A_SVT_OFF + nbuf * A_SVT_SZ + d * AVT_ROWB + c * 16,
                         Vtg + ((size_t)chh * DH + d) * LCHUNK + k0 + c * 8);
                }
            }
            cp_commit();
            cp_wait<1>();
        } else {
            cp_wait<0>();
        }
        __syncthreads();

        if (t == 0) {
#pragma unroll
            for (int kt = 0; kt < 5; kt++)
                ldmatrix4(qf[kt][0], qf[kt][1], qf[kt][2], qf[kt][3],
                          sb + A_SQ_OFF + (warp_m + a_row) * AQ_ROWB
                             + (kt * 16 + a_kof) * 2);
        }

        const uint32_t bK = sb + A_SK_OFF + buf * A_SK_SZ;
        const uint32_t bV = sb + A_SVT_OFF + buf * A_SVT_SZ;

        // ---- S = Q @ K^T : 8 n-tiles (keys) ----
        float sacc[8][4];
#pragma unroll
        for (int i = 0; i < 8; i++)
#pragma unroll
            for (int j = 0; j < 4; j++) sacc[i][j] = 0.f;

#pragma unroll
        for (int kt = 0; kt < 5; kt++) {
#pragma unroll
            for (int bp = 0; bp < 4; bp++) {
                uint32_t r0, r1, r2, r3;
                ldmatrix4(r0, r1, r2, r3,
                          bK + (bp * 16 + b_row) * AQ_ROWB + (kt * 16 + b_kof) * 2);
                mma16816(sacc[2 * bp][0], sacc[2 * bp][1],
                         sacc[2 * bp][2], sacc[2 * bp][3],
                         qf[kt][0], qf[kt][1], qf[kt][2], qf[kt][3], r0, r1);
                mma16816(sacc[2 * bp + 1][0], sacc[2 * bp + 1][1],
                         sacc[2 * bp + 1][2], sacc[2 * bp + 1][3],
                         qf[kt][0], qf[kt][1], qf[kt][2], qf[kt][3], r2, r3);
            }
        }

        // ---- online softmax (rows r=lane>>2 and r+8) ----
        float mx0 = -1e30f, mx1 = -1e30f;
#pragma unroll
        for (int i = 0; i < 8; i++) {
            mx0 = fmaxf(mx0, fmaxf(sacc[i][0], sacc[i][1]));
            mx1 = fmaxf(mx1, fmaxf(sacc[i][2], sacc[i][3]));
        }
        mx0 = fmaxf(mx0, __shfl_xor_sync(0xffffffffu, mx0, 1));
        mx0 = fmaxf(mx0, __shfl_xor_sync(0xffffffffu, mx0, 2));
        mx1 = fmaxf(mx1, __shfl_xor_sync(0xffffffffu, mx1, 1));
        mx1 = fmaxf(mx1, __shfl_xor_sync(0xffffffffu, mx1, 2));
        const float mn0 = fmaxf(m0, mx0);
        const float mn1 = fmaxf(m1, mx1);
        float la0 = 0.f, la1 = 0.f;
#pragma unroll
        for (int i = 0; i < 8; i++) {
            sacc[i][0] = __expf(sacc[i][0] - mn0);
            sacc[i][1] = __expf(sacc[i][1] - mn0);
            sacc[i][2] = __expf(sacc[i][2] - mn1);
            sacc[i][3] = __expf(sacc[i][3] - mn1);
            la0 += sacc[i][0] + sacc[i][1];
            la1 += sacc[i][2] + sacc[i][3];
        }
        la0 += __shfl_xor_sync(0xffffffffu, la0, 1);
        la0 += __shfl_xor_sync(0xffffffffu, la0, 2);
        la1 += __shfl_xor_sync(0xffffffffu, la1, 1);
        la1 += __shfl_xor_sync(0xffffffffu, la1, 2);
        const float sc0 = __expf(m0 - mn0);
        const float sc1 = __expf(m1 - mn1);
        l0 = l0 * sc0 + la0;  m0 = mn0;
        l1 = l1 * sc1 + la1;  m1 = mn1;
#pragma unroll
        for (int i = 0; i < 9; i++) {
            oacc[i][0] *= sc0; oacc[i][1] *= sc0;
            oacc[i][2] *= sc1; oacc[i][3] *= sc1;
        }

        // ---- pack P to fp16 A-fragments (C-layout == A-layout trick) ----
        uint32_t pf[4][4];
#pragma unroll
        for (int kt = 0; kt < 4; kt++) {
            pf[kt][0] = pack_h2(sacc[2 * kt][0],     sacc[2 * kt][1]);
            pf[kt][1] = pack_h2(sacc[2 * kt][2],     sacc[2 * kt][3]);
            pf[kt][2] = pack_h2(sacc[2 * kt + 1][0], sacc[2 * kt + 1][1]);
            pf[kt][3] = pack_h2(sacc[2 * kt + 1][2], sacc[2 * kt + 1][3]);
        }

        // ---- O += P @ V : 9 d n-tiles (tile 9 is pad, skipped) ----
#pragma unroll
        for (int kt = 0; kt < 4; kt++) {
#pragma unroll
            for (int bp = 0; bp < 5; bp++) {
                uint32_t r0, r1, r2, r3;
                ldmatrix4(r0, r1, r2, r3,
                          bV + (bp * 16 + b_row) * AVT_ROWB + (kt * 16 + b_kof) * 2);
                mma16816(oacc[2 * bp][0], oacc[2 * bp][1],
                         oacc[2 * bp][2], oacc[2 * bp][3],
                         pf[kt][0], pf[kt][1], pf[kt][2], pf[kt][3], r0, r1);
                if (bp < 4)
                    mma16816(oacc[2 * bp + 1][0], oacc[2 * bp + 1][1],
                             oacc[2 * bp + 1][2], oacc[2 * bp + 1][3],
                             pf[kt][0], pf[kt][1], pf[kt][2], pf[kt][3], r2, r3);
            }
        }
        __syncthreads();
    }

    // ---- epilogue ----
    const float inv0 = 1.f / l0;
    const float inv1 = 1.f / l1;
    const int r = lane >> 2;
    const size_t row0 = rowbase + q0 + warp_m + r;
    const int colb = h * DH + (lane & 3) * 2;
#pragma unroll
    for (int i = 0; i < 9; i++) {
        const int col = colb + i * 8;
        *(uint32_t*)(out + row0 * DMODEL + col) =
            pack_h2(oacc[i][0] * inv0, oacc[i][1] * inv0);
        *(uint32_t*)(out + (row0 + 8) * DMODEL + col) =
            pack_h2(oacc[i][2] * inv1, oacc[i][3] * inv1);
    }
}

// ---------------------------------------------------------------------------
// kernel_launch
// ---------------------------------------------------------------------------
extern "C" void kernel_launch(void* const* d_in, const int* in_sizes, int n_in,
                              void* d_out, int out_size)
{
    const float* hidden = (const float*)d_in[0];
    const float* cosp   = (const float*)d_in[1];
    const float* sinp   = (const float*)d_in[2];
    const float* qkv_w  = (const float*)d_in[3];
    const float* qkv_b  = (const float*)d_in[4];
    const float* proj_w = (const float*)d_in[5];
    const float* proj_b = (const float*)d_in[6];
    (void)in_sizes; (void)n_in;

    float*  qkv = nullptr;
    __half *hidden_h = nullptr, *qkvw_h = nullptr, *projw_h = nullptr;
    __half *qh = nullptr, *kh = nullptr, *vt = nullptr, *attn_h = nullptr;
    cudaGetSymbolAddress((void**)&qkv, g_qkv);
    cudaGetSymbolAddress((void**)&hidden_h, g_hidden_h);
    cudaGetSymbolAddress((void**)&qkvw_h, g_qkvw_h);
    cudaGetSymbolAddress((void**)&projw_h, g_projw_h);
    cudaGetSymbolAddress((void**)&qh, g_q_h);
    cudaGetSymbolAddress((void**)&kh, g_k_h);
    cudaGetSymbolAddress((void**)&vt, g_vt);
    cudaGetSymbolAddress((void**)&attn_h, g_attn_h);

    cudaFuncSetAttribute(attn_mma_kernel,
                         cudaFuncAttributeMaxDynamicSharedMemorySize,
                         A_SMEM_BYTES);

    // 0) fp32 -> fp16 conversions
    {
        const int n1 = SQ * DMODEL;
        cvt_f16_kernel<<<(n1 / 4 + 255) / 256, 256>>>(hidden, hidden_h, n1);
        const int n2 = QKV3 * DMODEL;
        cvt_f16_kernel<<<(n2 / 4 + 255) / 256, 256>>>(qkv_w, qkvw_h, n2);
        const int n3 = DMODEL * DMODEL;
        cvt_f16_kernel<<<(n3 / 4 + 255) / 256, 256>>>(proj_w, projw_h, n3);
    }

    // 1) QKV GEMM + bias (tensor cores)
    gemm_f16_kernel<<<dim3(QKV3 / BN, SQ / BM), 256>>>(
        hidden_h, qkvw_h, qkv_b, qkv, SQ, QKV3, DMODEL);

    // 2) RoPE + fp16 pack (Q scaled, K, V^T)
    {
        const int total = SQ * NH * (DH / 2);
        rope_pack_kernel<<<(total + 255) / 256, 256>>>(qkv, cosp, sinp, qh, kh, vt);
    }

    // 3) tensor-core flash attention
    attn_mma_kernel<<<dim3(LCHUNK / 128, NCHUNK * NH), 256, A_SMEM_BYTES>>>(
        qh, kh, vt, attn_h);

    // 4) output projection + bias (tensor cores)
    gemm_f16_kernel<<<dim3(DMODEL / BN, SQ / BM), 256>>>(
        attn_h, projw_h, proj_b, (float*)d_out, SQ, DMODEL, DMODEL);
}

// round 6
// speedup vs baseline: 7.7419x; 1.1109x over previous
#include <cuda_runtime.h>
#include <cuda_fp16.h>
#include <cstdint>

// Problem constants
#define SQ     8192
#define DMODEL 1152
#define NH     16
#define DH     72
#define QKV3   3456
#define LCHUNK 1024
#define NCHUNK 8

// Scratch (device globals; no cudaMalloc allowed)
__device__ __half g_qkv_h[(size_t)SQ * QKV3];      // fp16 qkv GEMM output
__device__ __half g_hidden_h[(size_t)SQ * DMODEL];
__device__ __half g_qkvw_h[(size_t)QKV3 * DMODEL];
__device__ __half g_projw_h[(size_t)DMODEL * DMODEL];
__device__ __half g_q_h[(size_t)SQ * DMODEL];      // roped+scaled Q fp16
__device__ __half g_k_h[(size_t)SQ * DMODEL];      // roped K fp16
__device__ __half g_vt[(size_t)NCHUNK * NH * DH * LCHUNK];  // V^T per (chunk,head)
__device__ __half g_attn_h[(size_t)SQ * DMODEL];   // attention output fp16

// ---------------------------------------------------------------------------
// common PTX helpers
// ---------------------------------------------------------------------------
__device__ __forceinline__ uint32_t smem_u32(const void* p) {
    uint32_t a;
    asm("{ .reg .u64 t; cvta.to.shared.u64 t, %1; cvt.u32.u64 %0, t; }"
        : "=r"(a) : "l"(p));
    return a;
}
__device__ __forceinline__ void cp16(uint32_t dst, const void* src) {
    asm volatile("cp.async.ca.shared.global [%0], [%1], 16;"
                 :: "r"(dst), "l"(src));
}
__device__ __forceinline__ void cp_commit() {
    asm volatile("cp.async.commit_group;");
}
template <int N>
__device__ __forceinline__ void cp_wait() {
    asm volatile("cp.async.wait_group %0;" :: "n"(N));
}
__device__ __forceinline__ void ldmatrix4(uint32_t& r0, uint32_t& r1,
                                          uint32_t& r2, uint32_t& r3,
                                          uint32_t addr) {
    asm volatile("ldmatrix.sync.aligned.m8n8.x4.shared.b16 {%0,%1,%2,%3}, [%4];"
                 : "=r"(r0), "=r"(r1), "=r"(r2), "=r"(r3) : "r"(addr));
}
__device__ __forceinline__ void mma16816(float& c0, float& c1, float& c2, float& c3,
                                         uint32_t a0, uint32_t a1, uint32_t a2, uint32_t a3,
                                         uint32_t b0, uint32_t b1) {
    asm volatile(
        "mma.sync.aligned.m16n8k16.row.col.f32.f16.f16.f32 "
        "{%0,%1,%2,%3}, {%4,%5,%6,%7}, {%8,%9}, {%0,%1,%2,%3};"
        : "+f"(c0), "+f"(c1), "+f"(c2), "+f"(c3)
        : "r"(a0), "r"(a1), "r"(a2), "r"(a3), "r"(b0), "r"(b1));
}
__device__ __forceinline__ uint32_t pack_h2(float lo, float hi) {
    uint32_t r;
    asm("cvt.rn.f16x2.f32 %0, %1, %2;" : "=r"(r) : "f"(hi), "f"(lo));
    return r;
}

// ---------------------------------------------------------------------------
// fp32 -> fp16 conversion
// ---------------------------------------------------------------------------
__global__ __launch_bounds__(256) void cvt_f16_kernel(
    const float* __restrict__ in, __half* __restrict__ out, int n)
{
    const int i = (blockIdx.x * blockDim.x + threadIdx.x) * 4;
    if (i >= n) return;
    const float4 v = *(const float4*)(in + i);
    __half2* o = (__half2*)(out + i);
    o[0] = __floats2half2_rn(v.x, v.y);
    o[1] = __floats2half2_rn(v.z, v.w);
}

// ---------------------------------------------------------------------------
// fp16 tensor-core GEMM: C = A @ W^T + bias.  Templated output (float / half).
// 128x128 block tile, BK=64 (half the barriers of BK=32), 256 threads,
// 8 warps at 64x32.  cp.async double-buffered dynamic smem, 144B rows.
// ---------------------------------------------------------------------------
#define BM 128
#define BN 128
#define BK 64
#define SROW 144                     // 64 halfs = 128B data + 16B pad
#define G_STAGE (BM * SROW)          // 18432 B per matrix per stage
#define GSM_BYTES (4 * G_STAGE)      // 73728

template <typename OutT>
__global__ __launch_bounds__(256) void gemm_f16_kernel(
    const __half* __restrict__ A, const __half* __restrict__ W,
    const float* __restrict__ bias, OutT* __restrict__ C,
    int M, int N, int K)
{
    extern __shared__ unsigned char gsm[];
    const uint32_t sA = smem_u32(gsm);               // A: stages 0,1
    const uint32_t sB = sA + 2 * G_STAGE;            // B: stages 0,1

    const int tid  = threadIdx.x;
    const int wid  = tid >> 5;
    const int lane = tid & 31;
    const int bm = blockIdx.y * BM;
    const int bn = blockIdx.x * BN;

    const int warp_m = (wid >> 2) * 64;
    const int warp_n = (wid & 3) * 32;

    const int nslab = K / BK;        // 18

    // loader: 1024 16B-chunks per matrix per stage; 4 per thread per matrix
    auto load_stage = [&](int buf, int k0) {
#pragma unroll
        for (int u = 0; u < 4; u++) {
            const int c = tid + u * 256;
            const int row = c >> 3, col = c & 7;
            cp16(sA + buf * G_STAGE + row * SROW + col * 16,
                 A + (size_t)(bm + row) * K + k0 + col * 8);
            cp16(sB + buf * G_STAGE + row * SROW + col * 16,
                 W + (size_t)(bn + row) * K + k0 + col * 8);
        }
        cp_commit();
    };

    load_stage(0, 0);

    float acc[4][4][4];
#pragma unroll
    for (int i = 0; i < 4; i++)
#pragma unroll
        for (int j = 0; j < 4; j++)
#pragma unroll
            for (int v = 0; v < 4; v++) acc[i][j][v] = 0.f;

    const int a_row = lane & 15;
    const int a_kof = (lane >> 4) * 8;
    const int b_row = ((lane >> 4) * 8) + (lane & 7);
    const int b_kof = ((lane >> 3) & 1) * 8;

    for (int s = 0; s < nslab; s++) {
        const int buf = s & 1;
        cp_wait<0>();
        __syncthreads();

        if (s + 1 < nslab)
            load_stage((s + 1) & 1, (s + 1) * BK);

        const uint32_t bA = sA + buf * G_STAGE;
        const uint32_t bB = sB + buf * G_STAGE;

#pragma unroll
        for (int ks = 0; ks < 4; ks++) {
            uint32_t af[4][4];
#pragma unroll
            for (int mt = 0; mt < 4; mt++)
                ldmatrix4(af[mt][0], af[mt][1], af[mt][2], af[mt][3],
                          bA + (warp_m + mt * 16 + a_row) * SROW
                             + (ks * 16 + a_kof) * 2);
            uint32_t bf[4][2];
#pragma unroll
            for (int nt2 = 0; nt2 < 2; nt2++) {
                uint32_t r0, r1, r2, r3;
                ldmatrix4(r0, r1, r2, r3,
                          bB + (warp_n + nt2 * 16 + b_row) * SROW
                             + (ks * 16 + b_kof) * 2);
                bf[nt2 * 2 + 0][0] = r0; bf[nt2 * 2 + 0][1] = r1;
                bf[nt2 * 2 + 1][0] = r2; bf[nt2 * 2 + 1][1] = r3;
            }
#pragma unroll
            for (int mt = 0; mt < 4; mt++)
#pragma unroll
                for (int nt = 0; nt < 4; nt++)
                    mma16816(acc[mt][nt][0], acc[mt][nt][1],
                             acc[mt][nt][2], acc[mt][nt][3],
                             af[mt][0], af[mt][1], af[mt][2], af[mt][3],
                             bf[nt][0], bf[nt][1]);
        }
        __syncthreads();
    }

    // epilogue: bias + store (fp32 or fp16)
    const int erow = lane >> 2;
    const int ecol = (lane & 3) * 2;
#pragma unroll
    for (int mt = 0; mt < 4; mt++) {
#pragma unroll
        for (int nt = 0; nt < 4; nt++) {
            const int col = bn + warp_n + nt * 8 + ecol;
            const float b0 = bias[col], b1 = bias[col + 1];
            const size_t r0 = (size_t)(bm + warp_m + mt * 16 + erow);
            if constexpr (sizeof(OutT) == 2) {
                *(uint32_t*)((__half*)C + r0 * N + col) =
                    pack_h2(acc[mt][nt][0] + b0, acc[mt][nt][1] + b1);
                *(uint32_t*)((__half*)C + (r0 + 8) * N + col) =
                    pack_h2(acc[mt][nt][2] + b0, acc[mt][nt][3] + b1);
            } else {
                *(float2*)((float*)C + r0 * N + col) =
                    make_float2(acc[mt][nt][0] + b0, acc[mt][nt][1] + b1);
                *(float2*)((float*)C + (r0 + 8) * N + col) =
                    make_float2(acc[mt][nt][2] + b0, acc[mt][nt][3] + b1);
            }
        }
    }
}

// ---------------------------------------------------------------------------
// RoPE + pack from fp16 qkv: -> fp16 Q (pre-scaled), fp16 K, fp16 V^T
// ---------------------------------------------------------------------------
__global__ __launch_bounds__(256) void rope_pack_kernel(
    const __half* __restrict__ qkv, const float* __restrict__ cosp,
    const float* __restrict__ sinp,
    __half* __restrict__ qh, __half* __restrict__ kh, __half* __restrict__ vt)
{
    const int idx = blockIdx.x * blockDim.x + threadIdx.x;
    const int total = SQ * NH * (DH / 2);
    if (idx >= total) return;
    const int d = idx % (DH / 2);
    const int t = idx / (DH / 2);
    const int h = t % NH;
    const int s = t / NH;

    const float c1 = cosp[s * DH + d];
    const float s1 = sinp[s * DH + d];
    const float c2 = cosp[s * DH + d + 36];
    const float s2 = sinp[s * DH + d + 36];
    const float scl = rsqrtf((float)DH);

    const size_t base = (size_t)s * QKV3 + h * DH;
    {
        const float x1 = __half2float(qkv[base + d]);
        const float x2 = __half2float(qkv[base + d + 36]);
        qh[(size_t)s * DMODEL + h * DH + d]      = __float2half_rn((x1 * c1 - x2 * s1) * scl);
        qh[(size_t)s * DMODEL + h * DH + d + 36] = __float2half_rn((x2 * c2 + x1 * s2) * scl);
    }
    {
        const float x1 = __half2float(qkv[base + DMODEL + d]);
        const float x2 = __half2float(qkv[base + DMODEL + d + 36]);
        kh[(size_t)s * DMODEL + h * DH + d]      = __float2half_rn(x1 * c1 - x2 * s1);
        kh[(size_t)s * DMODEL + h * DH + d + 36] = __float2half_rn(x2 * c2 + x1 * s2);
    }
    {
        const int chunk = s >> 10, sl = s & 1023;
        const size_t vb = ((size_t)(chunk * NH + h) * DH) * LCHUNK + sl;
        vt[vb + (size_t)d * LCHUNK]        = qkv[base + 2 * DMODEL + d];
        vt[vb + (size_t)(d + 36) * LCHUNK] = qkv[base + 2 * DMODEL + d + 36];
    }
}

// ---------------------------------------------------------------------------
// Tensor-core flash attention (R5, unchanged).
// ---------------------------------------------------------------------------
#define AQ_ROWB  176
#define AVT_ROWB 144
#define A_SQ_OFF  0
#define A_SK_OFF  (128 * AQ_ROWB)
#define A_SK_SZ   (64 * AQ_ROWB)
#define A_SVT_OFF (A_SK_OFF + 2 * A_SK_SZ)
#define A_SVT_SZ  (80 * AVT_ROWB)
#define A_SMEM_BYTES (A_SVT_OFF + 2 * A_SVT_SZ)

__global__ __launch_bounds__(256) void attn_mma_kernel(
    const __half* __restrict__ Qg, const __half* __restrict__ Kg,
    const __half* __restrict__ Vtg, __half* __restrict__ out)
{
    extern __shared__ unsigned char asmem[];
    const uint32_t sb = smem_u32(asmem);
    const int tid  = threadIdx.x;
    const int wid  = tid >> 5;
    const int lane = tid & 31;
    const int qt  = blockIdx.x;
    const int chh = blockIdx.y;
    const int chunk = chh >> 4, h = chh & 15;
    const size_t rowbase = (size_t)chunk * LCHUNK;
    const int q0 = qt * 128;
    const int warp_m = wid * 16;

    const uint4 z4 = make_uint4(0, 0, 0, 0);
    if (tid < 128)
        *(uint4*)(asmem + A_SQ_OFF + tid * AQ_ROWB + 144) = z4;
    else {
        const int t = tid - 128;
        *(uint4*)(asmem + A_SK_OFF + (t >> 6) * A_SK_SZ + (t & 63) * AQ_ROWB + 144) = z4;
    }
    for (int i = tid; i < 144; i += 256) {
        const int buf = i / 72, rem = i % 72;
        const int row = 72 + rem / 9, c = rem % 9;
        *(uint4*)(asmem + A_SVT_OFF + buf * A_SVT_SZ + row * AVT_ROWB + c * 16) = z4;
    }

    for (int i = tid; i < 128 * 9; i += 256) {
        const int row = i / 9, c = i % 9;
        cp16(sb + A_SQ_OFF + row * AQ_ROWB + c * 16,
             Qg + (rowbase + q0 + row) * DMODEL + h * DH + c * 8);
    }
    {
        for (int i = tid; i < 1152; i += 256) {
            if (i < 576) {
                const int row = i / 9, c = i % 9;
                cp16(sb + A_SK_OFF + row * AQ_ROWB + c * 16,
                     Kg + (rowbase + row) * DMODEL + h * DH + c * 8);
            } else {
                const int j = i - 576;
                const int d = j / 8, c = j % 8;
                cp16(sb + A_SVT_OFF + d * AVT_ROWB + c * 16,
                     Vtg + ((size_t)chh * DH + d) * LCHUNK + c * 8);
            }
        }
        cp_commit();
    }

    const int a_row = lane & 15;
    const int a_kof = (lane >> 4) * 8;
    const int b_row = ((lane >> 4) * 8) + (lane & 7);
    const int b_kof = ((lane >> 3) & 1) * 8;

    uint32_t qf[5][4];
    float oacc[9][4];
#pragma unroll
    for (int i = 0; i < 9; i++)
#pragma unroll
        for (int j = 0; j < 4; j++) oacc[i][j] = 0.f;
    float m0 = -1e30f, m1 = -1e30f, l0 = 0.f, l1 = 0.f;

    const int NTILE = LCHUNK / 64;

    for (int t = 0; t < NTILE; t++) {
        const int buf = t & 1;
        if (t + 1 < NTILE) {
            const int nbuf = (t + 1) & 1;
            const int k0 = (t + 1) * 64;
            for (int i = tid; i < 1152; i += 256) {
                if (i < 576) {
                    const int row = i / 9, c = i % 9;
                    cp16(sb + A_SK_OFF + nbuf * A_SK_SZ + row * AQ_ROWB + c * 16,
                         Kg + (rowbase + k0 + row) * DMODEL + h * DH + c * 8);
                } else {
                    const int j = i - 576;
                    const int d = j / 8, c = j % 8;
                    cp16(sb + A_SVT_OFF + nbuf * A_SVT_SZ + d * AVT_ROWB + c * 16,
                         Vtg + ((size_t)chh * DH + d) * LCHUNK + k0 + c * 8);
                }
            }
            cp_commit();
            cp_wait<1>();
        } else {
            cp_wait<0>();
        }
        __syncthreads();

        if (t == 0) {
#pragma unroll
            for (int kt = 0; kt < 5; kt++)
                ldmatrix4(qf[kt][0], qf[kt][1], qf[kt][2], qf[kt][3],
                          sb + A_SQ_OFF + (warp_m + a_row) * AQ_ROWB
                             + (kt * 16 + a_kof) * 2);
        }

        const uint32_t bK = sb + A_SK_OFF + buf * A_SK_SZ;
        const uint32_t bV = sb + A_SVT_OFF + buf * A_SVT_SZ;

        float sacc[8][4];
#pragma unroll
        for (int i = 0; i < 8; i++)
#pragma unroll
            for (int j = 0; j < 4; j++) sacc[i][j] = 0.f;

#pragma unroll
        for (int kt = 0; kt < 5; kt++) {
#pragma unroll
            for (int bp = 0; bp < 4; bp++) {
                uint32_t r0, r1, r2, r3;
                ldmatrix4(r0, r1, r2, r3,
                          bK + (bp * 16 + b_row) * AQ_ROWB + (kt * 16 + b_kof) * 2);
                mma16816(sacc[2 * bp][0], sacc[2 * bp][1],
                         sacc[2 * bp][2], sacc[2 * bp][3],
                         qf[kt][0], qf[kt][1], qf[kt][2], qf[kt][3], r0, r1);
                mma16816(sacc[2 * bp + 1][0], sacc[2 * bp + 1][1],
                         sacc[2 * bp + 1][2], sacc[2 * bp + 1][3],
                         qf[kt][0], qf[kt][1], qf[kt][2], qf[kt][3], r2, r3);
            }
        }

        float mx0 = -1e30f, mx1 = -1e30f;
#pragma unroll
        for (int i = 0; i < 8; i++) {
            mx0 = fmaxf(mx0, fmaxf(sacc[i][0], sacc[i][1]));
            mx1 = fmaxf(mx1, fmaxf(sacc[i][2], sacc[i][3]));
        }
        mx0 = fmaxf(mx0, __shfl_xor_sync(0xffffffffu, mx0, 1));
        mx0 = fmaxf(mx0, __shfl_xor_sync(0xffffffffu, mx0, 2));
        mx1 = fmaxf(mx1, __shfl_xor_sync(0xffffffffu, mx1, 1));
        mx1 = fmaxf(mx1, __shfl_xor_sync(0xffffffffu, mx1, 2));
        const float mn0 = fmaxf(m0, mx0);
        const float mn1 = fmaxf(m1, mx1);
        float la0 = 0.f, la1 = 0.f;
#pragma unroll
        for (int i = 0; i < 8; i++) {
            sacc[i][0] = __expf(sacc[i][0] - mn0);
            sacc[i][1] = __expf(sacc[i][1] - mn0);
            sacc[i][2] = __expf(sacc[i][2] - mn1);
            sacc[i][3] = __expf(sacc[i][3] - mn1);
            la0 += sacc[i][0] + sacc[i][1];
            la1 += sacc[i][2] + sacc[i][3];
        }
        la0 += __shfl_xor_sync(0xffffffffu, la0, 1);
        la0 += __shfl_xor_sync(0xffffffffu, la0, 2);
        la1 += __shfl_xor_sync(0xffffffffu, la1, 1);
        la1 += __shfl_xor_sync(0xffffffffu, la1, 2);
        const float sc0 = __expf(m0 - mn0);
        const float sc1 = __expf(m1 - mn1);
        l0 = l0 * sc0 + la0;  m0 = mn0;
        l1 = l1 * sc1 + la1;  m1 = mn1;
#pragma unroll
        for (int i = 0; i < 9; i++) {
            oacc[i][0] *= sc0; oacc[i][1] *= sc0;
            oacc[i][2] *= sc1; oacc[i][3] *= sc1;
        }

        uint32_t pf[4][4];
#pragma unroll
        for (int kt = 0; kt < 4; kt++) {
            pf[kt][0] = pack_h2(sacc[2 * kt][0],     sacc[2 * kt][1]);
            pf[kt][1] = pack_h2(sacc[2 * kt][2],     sacc[2 * kt][3]);
            pf[kt][2] = pack_h2(sacc[2 * kt + 1][0], sacc[2 * kt + 1][1]);
            pf[kt][3] = pack_h2(sacc[2 * kt + 1][2], sacc[2 * kt + 1][3]);
        }

#pragma unroll
        for (int kt = 0; kt < 4; kt++) {
#pragma unroll
            for (int bp = 0; bp < 5; bp++) {
                uint32_t r0, r1, r2, r3;
                ldmatrix4(r0, r1, r2, r3,
                          bV + (bp * 16 + b_row) * AVT_ROWB + (kt * 16 + b_kof) * 2);
                mma16816(oacc[2 * bp][0], oacc[2 * bp][1],
                         oacc[2 * bp][2], oacc[2 * bp][3],
                         pf[kt][0], pf[kt][1], pf[kt][2], pf[kt][3], r0, r1);
                if (bp < 4)
                    mma16816(oacc[2 * bp + 1][0], oacc[2 * bp + 1][1],
                             oacc[2 * bp + 1][2], oacc[2 * bp + 1][3],
                             pf[kt][0], pf[kt][1], pf[kt][2], pf[kt][3], r2, r3);
            }
        }
        __syncthreads();
    }

    const float inv0 = 1.f / l0;
    const float inv1 = 1.f / l1;
    const int r = lane >> 2;
    const size_t row0 = rowbase + q0 + warp_m + r;
    const int colb = h * DH + (lane & 3) * 2;
#pragma unroll
    for (int i = 0; i < 9; i++) {
        const int col = colb + i * 8;
        *(uint32_t*)(out + row0 * DMODEL + col) =
            pack_h2(oacc[i][0] * inv0, oacc[i][1] * inv0);
        *(uint32_t*)(out + (row0 + 8) * DMODEL + col) =
            pack_h2(oacc[i][2] * inv1, oacc[i][3] * inv1);
    }
}

// ---------------------------------------------------------------------------
// kernel_launch
// ---------------------------------------------------------------------------
extern "C" void kernel_launch(void* const* d_in, const int* in_sizes, int n_in,
                              void* d_out, int out_size)
{
    const float* hidden = (const float*)d_in[0];
    const float* cosp   = (const float*)d_in[1];
    const float* sinp   = (const float*)d_in[2];
    const float* qkv_w  = (const float*)d_in[3];
    const float* qkv_b  = (const float*)d_in[4];
    const float* proj_w = (const float*)d_in[5];
    const float* proj_b = (const float*)d_in[6];
    (void)in_sizes; (void)n_in;

    __half *qkv_h = nullptr, *hidden_h = nullptr, *qkvw_h = nullptr, *projw_h = nullptr;
    __half *qh = nullptr, *kh = nullptr, *vt = nullptr, *attn_h = nullptr;
    cudaGetSymbolAddress((void**)&qkv_h, g_qkv_h);
    cudaGetSymbolAddress((void**)&hidden_h, g_hidden_h);
    cudaGetSymbolAddress((void**)&qkvw_h, g_qkvw_h);
    cudaGetSymbolAddress((void**)&projw_h, g_projw_h);
    cudaGetSymbolAddress((void**)&qh, g_q_h);
    cudaGetSymbolAddress((void**)&kh, g_k_h);
    cudaGetSymbolAddress((void**)&vt, g_vt);
    cudaGetSymbolAddress((void**)&attn_h, g_attn_h);

    cudaFuncSetAttribute(gemm_f16_kernel<__half>,
                         cudaFuncAttributeMaxDynamicSharedMemorySize, GSM_BYTES);
    cudaFuncSetAttribute(gemm_f16_kernel<float>,
                         cudaFuncAttributeMaxDynamicSharedMemorySize, GSM_BYTES);
    cudaFuncSetAttribute(attn_mma_kernel,
                         cudaFuncAttributeMaxDynamicSharedMemorySize, A_SMEM_BYTES);

    // 0) fp32 -> fp16 conversions
    {
        const int n1 = SQ * DMODEL;
        cvt_f16_kernel<<<(n1 / 4 + 255) / 256, 256>>>(hidden, hidden_h, n1);
        const int n2 = QKV3 * DMODEL;
        cvt_f16_kernel<<<(n2 / 4 + 255) / 256, 256>>>(qkv_w, qkvw_h, n2);
        const int n3 = DMODEL * DMODEL;
        cvt_f16_kernel<<<(n3 / 4 + 255) / 256, 256>>>(proj_w, projw_h, n3);
    }

    // 1) QKV GEMM + bias -> fp16
    gemm_f16_kernel<__half><<<dim3(QKV3 / BN, SQ / BM), 256, GSM_BYTES>>>(
        hidden_h, qkvw_h, qkv_b, qkv_h, SQ, QKV3, DMODEL);

    // 2) RoPE + pack (Q scaled, K, V^T), fp16 in/out
    {
        const int total = SQ * NH * (DH / 2);
        rope_pack_kernel<<<(total + 255) / 256, 256>>>(qkv_h, cosp, sinp, qh, kh, vt);
    }

    // 3) tensor-core flash attention
    attn_mma_kernel<<<dim3(LCHUNK / 128, NCHUNK * NH), 256, A_SMEM_BYTES>>>(
        qh, kh, vt, attn_h);

    // 4) output projection + bias -> fp32 d_out
    gemm_f16_kernel<float><<<dim3(DMODEL / BN, SQ / BM), 256, GSM_BYTES>>>(
        attn_h, projw_h, proj_b, (float*)d_out, SQ, DMODEL, DMODEL);
}